// round 2
// baseline (speedup 1.0000x reference)
#include <cuda_runtime.h>
#include <cuda_bf16.h>

#define NCI 16
#define NCO 32
#define NBR 3
#define NTERM (NCI * 9 * NBR)   // 432
#define HH 32
#define WW 32
#define NBATCH 4

__device__ __forceinline__ float tanh_approx(float x) {
    float y;
    asm("tanh.approx.f32 %0, %1;" : "=f"(y) : "f"(x));
    return y;
}

// Fused kernel. Block = (b, co, 4-row tile), 64 threads = 32 cols x 2 row-pairs.
// Each thread computes 2 vertically-adjacent output pixels.
// Each block packs its own co's parameters into smem (prep fused in).
__global__ __launch_bounds__(64)
void ferro_main_kernel(const float* __restrict__ x,
                       const float* __restrict__ k,
                       const float* __restrict__ Ec,
                       const float* __restrict__ Ps,
                       const float* __restrict__ bias,
                       const float* __restrict__ coef,
                       const float* __restrict__ out_bias,
                       float* __restrict__ out) {
    __shared__ float4 sA[NTERM];              // {5Ec, k, 0.9kEc, 0.1kEc}
    __shared__ float  sC[NTERM];              // coef*Ps
    __shared__ float  sx[NCI][6][34];         // 6 input rows, 34 cols (zero pad)
    __shared__ float  sRed[2];

    int tid  = threadIdx.x;
    int tile = blockIdx.x & 7;                // 8 tiles of 4 output rows
    int co   = (blockIdx.x >> 3) & 31;
    int b    = blockIdx.x >> 8;
    int r0   = tile * 4;

    // ---- stage x tile: 16 ci x 6 rows x 32 cols, as float4 (768 float4 = 12*64)
    #pragma unroll
    for (int i = 0; i < 12; i++) {
        int idx = tid + i * 64;
        int c4  = idx & 7;
        int rr  = (idx >> 3) % 6;
        int ci  = idx / 48;
        int gr  = r0 - 1 + rr;
        float4 v = make_float4(0.f, 0.f, 0.f, 0.f);
        if ((unsigned)gr < 32u)
            v = *(const float4*)(x + (((b * NCI + ci) * HH + gr) * WW) + c4 * 4);
        int cb0 = c4 * 4 + 1;
        sx[ci][rr][cb0 + 0] = v.x;
        sx[ci][rr][cb0 + 1] = v.y;
        sx[ci][rr][cb0 + 2] = v.z;
        sx[ci][rr][cb0 + 3] = v.w;
    }
    // zero horizontal pad columns (96 rows)
    #pragma unroll
    for (int idx = tid; idx < NCI * 6; idx += 64) {
        int ci = idx / 6, rr = idx % 6;
        sx[ci][rr][0]  = 0.0f;
        sx[ci][rr][33] = 0.0f;
    }

    // ---- pack params for this co (432 terms = 108 float4 groups) + bias reduce
    const float4* k4 = (const float4*)(k    + co * NTERM);
    const float4* e4 = (const float4*)(Ec   + co * NTERM);
    const float4* p4 = (const float4*)(Ps   + co * NTERM);
    const float4* b4 = (const float4*)(bias + co * NTERM);
    const float4* c4p= (const float4*)(coef + co * NTERM);
    float cb = 0.0f;
    #pragma unroll
    for (int q = tid; q < NTERM / 4; q += 64) {
        float4 kk = k4[q], ee = e4[q], pp = p4[q], bb = b4[q], cc = c4p[q];
        float kkv[4] = {kk.x, kk.y, kk.z, kk.w};
        float eev[4] = {ee.x, ee.y, ee.z, ee.w};
        float ppv[4] = {pp.x, pp.y, pp.z, pp.w};
        float bbv[4] = {bb.x, bb.y, bb.z, bb.w};
        float ccv[4] = {cc.x, cc.y, cc.z, cc.w};
        #pragma unroll
        for (int j = 0; j < 4; j++) {
            int p = q * 4 + j;
            float ke = kkv[j] * eev[j];
            float4 a;
            a.x = 5.0f * eev[j];
            a.y = kkv[j];
            a.z = 0.9f * ke;
            a.w = 0.1f * ke;
            sA[p] = a;
            sC[p] = ccv[j] * ppv[j];
            cb += ccv[j] * bbv[j];
        }
    }
    // warp reduce cb, combine across the 2 warps via smem
    #pragma unroll
    for (int s = 16; s > 0; s >>= 1)
        cb += __shfl_xor_sync(0xFFFFFFFFu, cb, s);
    if ((tid & 31) == 0) sRed[tid >> 5] = cb;
    __syncthreads();

    float bc = sRed[0] + sRed[1] + out_bias[co];

    int wo = tid & 31;        // output col (lane -> conflict-free smem)
    int lr = tid >> 5;        // 0..1 -> output rows r0+2lr, r0+2lr+1

    float acc[6] = {0.f, 0.f, 0.f, 0.f, 0.f, 0.f};

    #pragma unroll 1
    for (int ci = 0; ci < NCI; ci++) {
        // 4 input rows x 3 cols shared by the two vertically adjacent pixels
        float xv[12];
        #pragma unroll
        for (int r = 0; r < 4; r++)
            #pragma unroll
            for (int c = 0; c < 3; c++)
                xv[r * 3 + c] = sx[ci][2 * lr + r][wo + c];

        #pragma unroll
        for (int nb = 0; nb < NBR; nb++) {
            #pragma unroll
            for (int ij = 0; ij < 9; ij++) {
                int idx = (ci * NBR + nb) * 9 + ij;   // raw [ci][nb][ij] order
                float4 a  = sA[idx];
                float  cp = sC[idx];
                int dy = ij / 3, dx = ij % 3;
                float x0 = xv[dy * 3 + dx];
                float x1 = xv[(dy + 1) * 3 + dx];
                float t10 = tanh_approx(fmaf(5.0f, x0, a.x));
                float t11 = tanh_approx(fmaf(5.0f, x1, a.x));
                float g0  = fmaf(a.y, x0, a.z);
                float g1  = fmaf(a.y, x1, a.z);
                float t20 = tanh_approx(fmaf(a.w, t10, g0));
                float t21 = tanh_approx(fmaf(a.w, t11, g1));
                acc[nb * 2 + 0] = fmaf(cp, t20, acc[nb * 2 + 0]);
                acc[nb * 2 + 1] = fmaf(cp, t21, acc[nb * 2 + 1]);
            }
        }
    }

    float r0v = (acc[0] + acc[2]) + (acc[4] + bc);
    float r1v = (acc[1] + acc[3]) + (acc[5] + bc);
    int ho = r0 + 2 * lr;
    float* op = out + (((b * NCO + co) * HH + ho) * WW) + wo;
    op[0]  = r0v;
    op[WW] = r1v;
}

extern "C" void kernel_launch(void* const* d_in, const int* in_sizes, int n_in,
                              void* d_out, int out_size) {
    const float* x        = (const float*)d_in[0];
    const float* k        = (const float*)d_in[1];
    const float* Ec       = (const float*)d_in[2];
    const float* Ps       = (const float*)d_in[3];
    const float* bias     = (const float*)d_in[4];
    const float* coef     = (const float*)d_in[5];
    const float* out_bias = (const float*)d_in[6];
    float* out = (float*)d_out;

    ferro_main_kernel<<<NBATCH * NCO * 8, 64>>>(x, k, Ec, Ps, bias, coef, out_bias, out);
}

// round 3
// speedup vs baseline: 1.1862x; 1.1862x over previous
#include <cuda_runtime.h>
#include <cuda_bf16.h>

#define NCI 16
#define NCO 32
#define NBR 3
#define NTERM (NCI * 9 * NBR)   // 432 per co
#define HH 32
#define WW 32
#define NBATCH 4

__device__ __forceinline__ float tanh_approx(float x) {
    float y;
    asm("tanh.approx.f32 %0, %1;" : "=f"(y) : "f"(x));
    return y;
}

// Block = (b, co, 4-row tile). 128 threads = 2 ci-groups x 64 threads.
// Each thread: 2 vertically adjacent pixels, 8 of 16 input channels.
// Cross-group combine through smem at the end.
__global__ __launch_bounds__(128, 7)
void ferro_main_kernel(const float* __restrict__ x,
                       const float* __restrict__ k,
                       const float* __restrict__ Ec,
                       const float* __restrict__ Ps,
                       const float* __restrict__ bias,
                       const float* __restrict__ coef,
                       const float* __restrict__ out_bias,
                       float* __restrict__ out) {
    __shared__ float4 sA[NTERM];        // {5Ec, k, 0.1kEc, coef*Ps}
    __shared__ float  sx[NCI][6][34];   // 6 input rows, 34 cols (zero padded)
    __shared__ float  sP[64][2];        // group-1 partials
    __shared__ float  sRed[4];

    int tid  = threadIdx.x;
    int tile = blockIdx.x & 7;          // 8 tiles of 4 output rows
    int co   = (blockIdx.x >> 3) & 31;
    int b    = blockIdx.x >> 8;
    int r0   = tile * 4;

    // ---- stage x tile: 16 ci x 6 rows x 8 float4 = 768 float4 (6 per thread)
    #pragma unroll
    for (int i = 0; i < 6; i++) {
        int idx = tid + i * 128;
        int c4  = idx & 7;
        int rr  = (idx >> 3) % 6;
        int ci  = idx / 48;
        int gr  = r0 - 1 + rr;
        float4 v = make_float4(0.f, 0.f, 0.f, 0.f);
        if ((unsigned)gr < 32u)
            v = *(const float4*)(x + (((b * NCI + ci) * HH + gr) * WW) + c4 * 4);
        int cb0 = c4 * 4 + 1;
        sx[ci][rr][cb0 + 0] = v.x;
        sx[ci][rr][cb0 + 1] = v.y;
        sx[ci][rr][cb0 + 2] = v.z;
        sx[ci][rr][cb0 + 3] = v.w;
    }
    if (tid < 96) {                     // zero the 96 pad-column pairs
        int ci = tid / 6, rr = tid % 6;
        sx[ci][rr][0]  = 0.0f;
        sx[ci][rr][33] = 0.0f;
    }

    // ---- pack params for this co (432 terms = 108 float4 groups)
    float cb = 0.0f;
    if (tid < NTERM / 4) {
        const float4* k4 = (const float4*)(k    + co * NTERM);
        const float4* e4 = (const float4*)(Ec   + co * NTERM);
        const float4* p4 = (const float4*)(Ps   + co * NTERM);
        const float4* b4 = (const float4*)(bias + co * NTERM);
        const float4* c4 = (const float4*)(coef + co * NTERM);
        float4 kk = k4[tid], ee = e4[tid], pp = p4[tid], bb = b4[tid], cc = c4[tid];
        float kkv[4] = {kk.x, kk.y, kk.z, kk.w};
        float eev[4] = {ee.x, ee.y, ee.z, ee.w};
        float ppv[4] = {pp.x, pp.y, pp.z, pp.w};
        float bbv[4] = {bb.x, bb.y, bb.z, bb.w};
        float ccv[4] = {cc.x, cc.y, cc.z, cc.w};
        #pragma unroll
        for (int j = 0; j < 4; j++) {
            float4 a;
            a.x = 5.0f * eev[j];
            a.y = kkv[j];
            a.z = 0.1f * kkv[j] * eev[j];   // note: 0.9kEc = 9 * a.z
            a.w = ccv[j] * ppv[j];
            sA[tid * 4 + j] = a;
            cb += ccv[j] * bbv[j];
        }
    }
    // block-reduce cb (position-independent term)
    #pragma unroll
    for (int s = 16; s > 0; s >>= 1)
        cb += __shfl_xor_sync(0xFFFFFFFFu, cb, s);
    if ((tid & 31) == 0) sRed[tid >> 5] = cb;
    __syncthreads();
    float bc = (sRed[0] + sRed[1]) + (sRed[2] + sRed[3]) + out_bias[co];

    int cig = tid >> 6;       // ci-group: 0 or 1 (8 channels each)
    int t   = tid & 63;
    int wo  = t & 31;         // output col
    int lr  = t >> 5;         // 0..1 -> rows r0+2lr, r0+2lr+1

    float acc[6] = {0.f, 0.f, 0.f, 0.f, 0.f, 0.f};

    #pragma unroll 1
    for (int ci8 = 0; ci8 < 8; ci8++) {
        int ci = cig * 8 + ci8;
        // 4 input rows x 3 cols shared by the vertical pixel pair
        float xv[12];
        #pragma unroll
        for (int r = 0; r < 4; r++)
            #pragma unroll
            for (int c = 0; c < 3; c++)
                xv[r * 3 + c] = sx[ci][2 * lr + r][wo + c];

        const float4* pa = &sA[ci * 27];
        #pragma unroll
        for (int nb = 0; nb < NBR; nb++) {
            #pragma unroll
            for (int ij = 0; ij < 9; ij++) {
                float4 a = pa[nb * 9 + ij];
                int dy = ij / 3, dx = ij % 3;
                float x0 = xv[dy * 3 + dx];
                float x1 = xv[(dy + 1) * 3 + dx];
                float t10 = tanh_approx(fmaf(5.0f, x0, a.x));
                float t11 = tanh_approx(fmaf(5.0f, x1, a.x));
                float m0  = a.y * x0;
                float m1  = a.y * x1;
                float t20 = tanh_approx(fmaf(a.z, t10 + 9.0f, m0));
                float t21 = tanh_approx(fmaf(a.z, t11 + 9.0f, m1));
                acc[nb * 2 + 0] = fmaf(a.w, t20, acc[nb * 2 + 0]);
                acc[nb * 2 + 1] = fmaf(a.w, t21, acc[nb * 2 + 1]);
            }
        }
    }

    float r0v = (acc[0] + acc[2]) + acc[4];
    float r1v = (acc[1] + acc[3]) + acc[5];

    if (cig == 1) {
        sP[t][0] = r0v;
        sP[t][1] = r1v;
    }
    __syncthreads();
    if (cig == 0) {
        int ho = r0 + 2 * lr;
        float* op = out + (((b * NCO + co) * HH + ho) * WW) + wo;
        op[0]  = (r0v + sP[t][0]) + bc;
        op[WW] = (r1v + sP[t][1]) + bc;
    }
}

extern "C" void kernel_launch(void* const* d_in, const int* in_sizes, int n_in,
                              void* d_out, int out_size) {
    const float* x        = (const float*)d_in[0];
    const float* k        = (const float*)d_in[1];
    const float* Ec       = (const float*)d_in[2];
    const float* Ps       = (const float*)d_in[3];
    const float* bias     = (const float*)d_in[4];
    const float* coef     = (const float*)d_in[5];
    const float* out_bias = (const float*)d_in[6];
    float* out = (float*)d_out;

    ferro_main_kernel<<<NBATCH * NCO * 8, 128>>>(x, k, Ec, Ps, bias, coef, out_bias, out);
}